// round 14
// baseline (speedup 1.0000x reference)
#include <cuda_runtime.h>
#include <cuda_fp16.h>
#include <cstdint>
#include <cstddef>

// Problem constants: S=1024, B=4, E=1024, H=16, D=64
#define S_LEN   1024
#define BATCH   4
#define NHEADS  16
#define DHEAD   64
#define NBH     64          // BATCH*NHEADS
#define NROWS   4096        // S*B
#define EMB     1024

typedef unsigned long long ull;

// ---------------- scratch (device globals; no allocation allowed) ----------
// fp16 2-pass split operands (K_eff = 2048):
//   A2 = [Ahi | Ahi]  (activations: hi duplicated),  W2 = [Whi | Wlo]
//   dot(A2,W2) = Ahi.Whi + Ahi.Wlo   (drops Alo.Whi ~ 2^-12 relative)
__device__ __half g_a2   [(size_t)4096 * 2048];
__device__ __half g_w2in [(size_t)3072 * 2048];
__device__ __half g_w2out[(size_t)1024 * 2048];

// q: fp16 hi-only [bh][s][64]; k/v: fp16 hi+lo planes [bh][plane][s][64]
__device__ __half g_qh[(size_t)NBH * S_LEN * DHEAD];
__device__ __half g_k2[(size_t)NBH * 2 * S_LEN * DHEAD];
__device__ __half g_v2[(size_t)NBH * 2 * S_LEN * DHEAD];

// ---------------- baseline-PTX async-copy / ldmatrix / mma -----------------
__device__ __forceinline__ uint32_t smem_u32(const void* p) {
    uint32_t a;
    asm("{ .reg .u64 t; cvta.to.shared.u64 t, %1; cvt.u32.u64 %0, t; }" : "=r"(a) : "l"(p));
    return a;
}
__device__ __forceinline__ void cp_async16(uint32_t saddr, const void* g) {
    asm volatile("cp.async.cg.shared.global [%0], [%1], 16;" :: "r"(saddr), "l"(g));
}
#define CP_COMMIT() asm volatile("cp.async.commit_group;" ::: "memory")
#define CP_WAIT0()  asm volatile("cp.async.wait_group 0;" ::: "memory")

__device__ __forceinline__ void pf_l2(const void* p) {
    asm volatile("prefetch.global.L2 [%0];" :: "l"(p));
}

__device__ __forceinline__ void ldsm_x4(uint32_t& r0, uint32_t& r1, uint32_t& r2, uint32_t& r3,
                                        uint32_t addr) {
    asm volatile("ldmatrix.sync.aligned.m8n8.x4.shared.b16 {%0,%1,%2,%3}, [%4];"
                 : "=r"(r0), "=r"(r1), "=r"(r2), "=r"(r3) : "r"(addr));
}
__device__ __forceinline__ void ldsm_x4t(uint32_t& r0, uint32_t& r1, uint32_t& r2, uint32_t& r3,
                                         uint32_t addr) {
    asm volatile("ldmatrix.sync.aligned.m8n8.x4.trans.shared.b16 {%0,%1,%2,%3}, [%4];"
                 : "=r"(r0), "=r"(r1), "=r"(r2), "=r"(r3) : "r"(addr));
}
__device__ __forceinline__ void mma16816(float* c, const uint32_t* a, const uint32_t* b) {
    asm volatile("mma.sync.aligned.m16n8k16.row.col.f32.f16.f16.f32 "
                 "{%0,%1,%2,%3}, {%4,%5,%6,%7}, {%8,%9}, {%0,%1,%2,%3};"
                 : "+f"(c[0]), "+f"(c[1]), "+f"(c[2]), "+f"(c[3])
                 : "r"(a[0]), "r"(a[1]), "r"(a[2]), "r"(a[3]), "r"(b[0]), "r"(b[1]));
}
__device__ __forceinline__ unsigned pack_h(__half a, __half b) {
    return (unsigned)__half_as_ushort(a) | ((unsigned)__half_as_ushort(b) << 16);
}
__device__ __forceinline__ void split2h(float x, float y, unsigned& hi, unsigned& lo) {
    __half hx = __float2half(x), hy = __float2half(y);
    hi = pack_h(hx, hy);
    lo = pack_h(__float2half(x - __half2float(hx)),
                __float2half(y - __half2float(hy)));
}

// ===========================================================================
// Split conversion: src fp32 [rows x 1024] -> dst fp16 [rows x 2048].
// STYLE 0 (activations): [hi | hi].  STYLE 1 (weights): [hi | lo].
// ===========================================================================
template <int STYLE>
__global__ void split_kernel(const float* __restrict__ src, __half* __restrict__ dst)
{
    int idx = blockIdx.x * 256 + threadIdx.x;       // one k-pair
    int r = idx >> 9, kp = idx & 511;
    float2 v = *(const float2*)(src + (size_t)r * 1024 + kp * 2);
    unsigned hp, lp;
    split2h(v.x, v.y, hp, lp);
    size_t base = (size_t)r * 2048 + kp * 2;
    *(unsigned*)(dst + base)        = hp;
    *(unsigned*)(dst + base + 1024) = (STYLE == 0) ? hp : lp;
}

// ===========================================================================
// mma.sync fp16 GEMM over K_eff=2048 (R11/R13-measured: ~140us, tensor 60.7%).
// Block 128x128, 128 threads (4 warps as 2m x 2n), warp tile 64x64.
// BK=64 (128B rows, full swizzle g^(row&7)), 2-stage double buffer in 64KB
// dynamic SMEM -> 32 stages.  UNCHANGED.
// MODE 0: epilogue writes q (fp16 hi), k/v (fp16 hi+lo planes); q scaled 0.125.
// MODE 1: epilogue writes fp32 Cout.
// ===========================================================================
#define GEMM_SMEM 65536     // sA 2x16K at [0,32K), sB 2x16K at [32K,64K)

template <int MODE>
__global__ __launch_bounds__(128, 2)
void gemm_ms(const float* __restrict__ bias, float* __restrict__ Cout)
{
    constexpr int KE = 2048;
    constexpr int NS = KE / 64;     // 32 stages
    extern __shared__ __align__(16) char gsm[];
    const uint32_t sbA = smem_u32(gsm);
    const uint32_t sbB = sbA + 32768;

    const __half* __restrict__ A2 = g_a2;
    const __half* __restrict__ B2 = (MODE == 0) ? g_w2in : g_w2out;

    const int tid = threadIdx.x;
    const int wid = tid >> 5, lane = tid & 31;
    const int wm = wid & 1, wn = wid >> 1;           // 2m x 2n warps
    const int m0 = blockIdx.y * 128, n0 = blockIdx.x * 128;

    float c[4][8][4];
#pragma unroll
    for (int i = 0; i < 4; i++)
#pragma unroll
        for (int j = 0; j < 8; j++)
#pragma unroll
            for (int r = 0; r < 4; r++) c[i][j][r] = 0.f;

    // stage loader: 1024 granules (16B) per matrix; 8 per thread per matrix.
    // swizzle: granule' = granule ^ (row & 7)   (128B rows)
    auto loadStage = [&](int st, int k0) {
        uint32_t baseA = sbA + st * 16384;
        uint32_t baseB = sbB + st * 16384;
#pragma unroll
        for (int h = 0; h < 8; h++) {
            int g = tid + 128 * h;
            int row = g >> 3, gc = g & 7;
            int sw = gc ^ (row & 7);
            cp_async16(baseA + row * 128 + sw * 16, A2 + (size_t)(m0 + row) * KE + k0 + gc * 8);
            cp_async16(baseB + row * 128 + sw * 16, B2 + (size_t)(n0 + row) * KE + k0 + gc * 8);
        }
    };

    loadStage(0, 0);
    CP_COMMIT();

    for (int s = 0; s < NS; s++) {
        CP_WAIT0();
        __syncthreads();
        if (s + 1 < NS) {
            loadStage((s + 1) & 1, (s + 1) * 64);
            CP_COMMIT();
        }
        const int st = s & 1;
        const uint32_t baseA = sbA + st * 16384;
        const uint32_t baseB = sbB + st * 16384;

#pragma unroll
        for (int j = 0; j < 4; j++) {          // four k16 sub-steps
            uint32_t a[4][4];
#pragma unroll
            for (int mf = 0; mf < 4; mf++) {
                int row = wm * 64 + mf * 16 + (lane & 15);
                int g = j * 2 + (lane >> 4);
                int sw = g ^ (row & 7);
                ldsm_x4(a[mf][0], a[mf][1], a[mf][2], a[mf][3], baseA + row * 128 + sw * 16);
            }
            uint32_t b[8][2];
#pragma unroll
            for (int p = 0; p < 4; p++) {      // pair of n8 frags per ldsm.x4
                int row = wn * 64 + p * 16 + (lane & 7) + ((lane >> 4) << 3);
                int g = j * 2 + ((lane >> 3) & 1);
                int sw = g ^ (row & 7);
                uint32_t r0, r1, r2, r3;
                ldsm_x4(r0, r1, r2, r3, baseB + row * 128 + sw * 16);
                b[p * 2][0] = r0; b[p * 2][1] = r1;
                b[p * 2 + 1][0] = r2; b[p * 2 + 1][1] = r3;
            }
#pragma unroll
            for (int mf = 0; mf < 4; mf++)
#pragma unroll
                for (int nf = 0; nf < 8; nf++)
                    mma16816(c[mf][nf], a[mf], b[nf]);
        }
        __syncthreads();
    }

    // ---- epilogue: thread holds rows {t/4, t/4+8}, col pair (t%4)*2
#pragma unroll
    for (int mf = 0; mf < 4; mf++) {
#pragma unroll
        for (int nf = 0; nf < 8; nf++) {
            int n = n0 + wn * 64 + nf * 8 + (lane & 3) * 2;
            float2 bb = *(const float2*)(bias + n);
#pragma unroll
            for (int half = 0; half < 2; half++) {
                int m = m0 + wm * 64 + mf * 16 + (lane >> 2) + half * 8;
                float vx = c[mf][nf][half * 2 + 0] + bb.x;
                float vy = c[mf][nf][half * 2 + 1] + bb.y;
                if (MODE == 0) {
                    int sI = m >> 2, bI = m & 3;
                    int h = n / 192, t = n % 192;
                    int bhI = bI * NHEADS + h;
                    if (t < 64) {
                        vx *= 0.125f; vy *= 0.125f;
                        *(unsigned*)(g_qh + (size_t)bhI * 65536 + (size_t)sI * 64 + t)
                            = pack_h(__float2half(vx), __float2half(vy));
                    } else {
                        __half* dst = (t < 128) ? g_k2 : g_v2;
                        int d = (t < 128) ? (t - 64) : (t - 128);
                        unsigned hi, lo;
                        split2h(vx, vy, hi, lo);
                        size_t base = (size_t)bhI * 131072 + (size_t)sI * 64 + d;
                        *(unsigned*)(dst + base)         = hi;
                        *(unsigned*)(dst + base + 65536) = lo;
                    }
                } else {
                    *(float2*)(Cout + (size_t)m * EMB + n) = make_float2(vx, vy);
                }
            }
        }
    }
}

// ===========================================================================
// Tensor-core fused attention, fp16 2-pass math + double-buffered K/V
// (R13-proven) + L2 PREFETCH of next chunk's bias/mul (this round's change).
// Each thread prefetches exactly the 32 gmem addresses it will __ldg in the
// next chunk's softmax passes -> point-of-use loads become L2 hits.
// Block = 128 q rows x full 1024 keys (16 chunks of 64).
// 8 warps; warp w owns q rows [16w,16w+16) -> softmax stats warp-local.
// fp16: scores = Qhi.(Khi+Klo);  O += Phi.(Vhi+Vlo)
// softmax_1 exact via running-max init 0 (phantom +1 = exp(-m_final)).
// SMEM 96KB: Qh 16K | KV buf0 32K | KV buf1 32K | Ph 16K   (2 CTA/SM)
//   KV buf layout: Kh +0, Kl +8K, Vh +16K, Vl +24K
// Output written directly in g_a2 [hi|hi] format for gemm_ms<1>.
// ===========================================================================
#define SM_QH  0
#define SM_KV  16384
#define SM_PH  81920
#define ATT_SMEM 98304

__global__ __launch_bounds__(256, 2)
void attn_mma(const float* __restrict__ abias, const float* __restrict__ amul,
              const int* __restrict__ kpm)
{
    extern __shared__ __align__(16) char sm[];
    const uint32_t sb = smem_u32(sm);
    const int tid = threadIdx.x;
    const int w = tid >> 5, lane = tid & 31;
    const int bh = blockIdx.y;
    const int q0 = blockIdx.x * 128;
    const int bI = bh >> 4, h = bh & 15;

    const __half* qsrc = g_qh + (size_t)bh * 65536;
    const __half* ksrc = g_k2 + (size_t)bh * 131072;
    const __half* vsrc = g_v2 + (size_t)bh * 131072;

    // K/V chunk loader: 2048 granules (2 planes K + 2 planes V), 8/thread
    auto kvload = [&](int buf, int k0) {
        uint32_t base = sb + SM_KV + buf * 32768;
#pragma unroll
        for (int i = 0; i < 8; i++) {
            int g = tid + 256 * i;
            int plane = g >> 9, r = (g >> 3) & 63, gc = g & 7;
            const __half* src = (plane < 2 ? ksrc : vsrc) + (plane & 1) * 65536
                                + (size_t)(k0 + r) * 64 + gc * 8;
            cp_async16(base + plane * 8192 + r * 128 + ((gc ^ (r & 7)) << 4), src);
        }
    };

    // Q hi plane (persists whole kernel): 1024 x 16B granules, swizzle g^(row&7)
#pragma unroll
    for (int i = 0; i < 4; i++) {
        int g = tid + 256 * i;
        int r = g >> 3, gc = g & 7;
        cp_async16(sb + SM_QH + r * 128 + ((gc ^ (r & 7)) << 4),
                   qsrc + (size_t)(q0 + r) * 64 + gc * 8);
    }
    CP_COMMIT();           // group: Q
    kvload(0, 0);
    CP_COMMIT();           // group: KV0

    float o[8][4];
#pragma unroll
    for (int i = 0; i < 8; i++)
#pragma unroll
        for (int r = 0; r < 4; r++) o[i][r] = 0.f;
    float mr0 = 0.f, mr1 = 0.f, ls0 = 0.f, ls1 = 0.f;   // running max/sum (phantom 0)

    const int rA = lane >> 2;          // 0..7: first fragment row
    const int cA = (lane & 3) * 2;     // col pair base

    // per-thread gmem row bases for bias/mul (k-offset added per chunk)
    const int qg0 = q0 + w * 16 + rA;
    const size_t boB = ((size_t)bh * S_LEN + qg0) * S_LEN + cA;

    // prefetch chunk 0's bias/mul while Q/KV0 are in flight
#pragma unroll
    for (int nf = 0; nf < 8; nf++) {
        size_t off0 = boB + nf * 8;
        size_t off1 = off0 + (size_t)8 * S_LEN;
        pf_l2(abias + off0); pf_l2(abias + off1);
        pf_l2(amul + off0);  pf_l2(amul + off1);
    }

    for (int chunk = 0; chunk < 16; chunk++) {
        const int k0 = chunk * 64;
        CP_WAIT0();            // KV_c (and Q on chunk 0) landed
        __syncthreads();       // visible to all; buf (c+1)&1 free (read finished in c-1)
        if (chunk + 1 < 16) {
            kvload((chunk + 1) & 1, k0 + 64);
            CP_COMMIT();
            // L2-prefetch next chunk's bias/mul (exact future __ldg addresses)
#pragma unroll
            for (int nf = 0; nf < 8; nf++) {
                size_t off0 = boB + k0 + 64 + nf * 8;
                size_t off1 = off0 + (size_t)8 * S_LEN;
                pf_l2(abias + off0); pf_l2(abias + off1);
                pf_l2(amul + off0);  pf_l2(amul + off1);
            }
        }
        const uint32_t kvb = sb + SM_KV + (chunk & 1) * 32768;

        // ---- scores: c = Qhi.(Khi + Klo)
        float c[8][4];
#pragma unroll
        for (int i = 0; i < 8; i++)
#pragma unroll
            for (int r = 0; r < 4; r++) c[i][r] = 0.f;
#pragma unroll
        for (int j = 0; j < 4; j++) {
            uint32_t qH[4];
            {
                int r = w * 16 + (lane & 15);
                int g = j * 2 + (lane >> 4);
                int s_ = g ^ (r & 7);
                ldsm_x4(qH[0], qH[1], qH[2], qH[3], sb + SM_QH + r * 128 + s_ * 16);
            }
#pragma unroll
            for (int p = 0; p < 4; p++) {
                int r = p * 16 + (lane & 7) + ((lane >> 4) << 3);
                int g = j * 2 + ((lane >> 3) & 1);
                int s_ = g ^ (r & 7);
                uint32_t b0, b1, b2, b3, bb[2];
                ldsm_x4(b0, b1, b2, b3, kvb + r * 128 + s_ * 16);            // Khi
                bb[0] = b0; bb[1] = b1; mma16816(c[2 * p], qH, bb);
                bb[0] = b2; bb[1] = b3; mma16816(c[2 * p + 1], qH, bb);
                ldsm_x4(b0, b1, b2, b3, kvb + 8192 + r * 128 + s_ * 16);     // Klo
                bb[0] = b0; bb[1] = b1; mma16816(c[2 * p], qH, bb);
                bb[0] = b2; bb[1] = b3; mma16816(c[2 * p + 1], qH, bb);
            }
        }

        // ---- softmax pass 1: + bias, mask, chunk row-max
        const size_t bo0 = boB + k0;
        const size_t bo1 = bo0 + (size_t)8 * S_LEN;
        float cm0 = -1e30f, cm1 = -1e30f;
#pragma unroll
        for (int nf = 0; nf < 8; nf++) {
            int2 mk = __ldg((const int2*)(kpm + bI * S_LEN + k0 + nf * 8 + cA));
            float2 bA = __ldg((const float2*)(abias + bo0 + nf * 8));
            float2 bB = __ldg((const float2*)(abias + bo1 + nf * 8));
            c[nf][0] += bA.x; c[nf][1] += bA.y; c[nf][2] += bB.x; c[nf][3] += bB.y;
            if (mk.x) { c[nf][0] = -1e30f; c[nf][2] = -1e30f; }
            if (mk.y) { c[nf][1] = -1e30f; c[nf][3] = -1e30f; }
            cm0 = fmaxf(cm0, fmaxf(c[nf][0], c[nf][1]));
            cm1 = fmaxf(cm1, fmaxf(c[nf][2], c[nf][3]));
        }
        cm0 = fmaxf(cm0, __shfl_xor_sync(0xffffffffu, cm0, 1));
        cm0 = fmaxf(cm0, __shfl_xor_sync(0xffffffffu, cm0, 2));
        cm1 = fmaxf(cm1, __shfl_xor_sync(0xffffffffu, cm1, 1));
        cm1 = fmaxf(cm1, __shfl_xor_sync(0xffffffffu, cm1, 2));
        float nm0 = fmaxf(mr0, cm0), nm1 = fmaxf(mr1, cm1);
        float al0 = __expf(mr0 - nm0), al1 = __expf(mr1 - nm1);
        mr0 = nm0; mr1 = nm1;

        // ---- pass 2: exp, *mul, store P (fp16 hi only); accumulate l
        float s0 = 0.f, s1 = 0.f;
        const int r0 = w * 16 + rA, r1 = r0 + 8;
#pragma unroll
        for (int nf = 0; nf < 8; nf++) {
            float2 mA = __ldg((const float2*)(amul + bo0 + nf * 8));
            float2 mB = __ldg((const float2*)(amul + bo1 + nf * 8));
            float e0 = __expf(c[nf][0] - nm0), e1 = __expf(c[nf][1] - nm0);
            float e2 = __expf(c[nf][2] - nm1), e3 = __expf(c[nf][3] - nm1);
            s0 += e0 + e1; s1 += e2 + e3;
            float p0 = e0 * mA.x, p1 = e1 * mA.y, p2 = e2 * mB.x, p3 = e3 * mB.y;
            int col = nf * 8 + cA;
            int gc = col >> 3, cb = (col & 7) * 2;
            *(unsigned*)(sm + SM_PH + r0 * 128 + ((gc ^ (r0 & 7)) << 4) + cb)
                = pack_h(__float2half(p0), __float2half(p1));
            *(unsigned*)(sm + SM_PH + r1 * 128 + ((gc ^ (r1 & 7)) << 4) + cb)
                = pack_h(__float2half(p2), __float2half(p3));
        }
        ls0 = ls0 * al0 + s0;
        ls1 = ls1 * al1 + s1;
#pragma unroll
        for (int nf = 0; nf < 8; nf++) {
            o[nf][0] *= al0; o[nf][1] *= al0;
            o[nf][2] *= al1; o[nf][3] *= al1;
        }
        __syncwarp();   // P rows are warp-private

        // ---- O += Phi.(Vhi + Vlo)  (ldmatrix.trans for V)
#pragma unroll
        for (int j = 0; j < 4; j++) {
            uint32_t aH[4];
            {
                int r = w * 16 + (lane & 15);
                int g = j * 2 + (lane >> 4);
                int s_ = g ^ (r & 7);
                ldsm_x4(aH[0], aH[1], aH[2], aH[3], sb + SM_PH + r * 128 + s_ * 16);
            }
#pragma unroll
            for (int p = 0; p < 4; p++) {
                int kr = j * 16 + ((lane >> 3) & 1) * 8 + (lane & 7);
                int g = p * 2 + ((lane >> 4) & 1);
                int s_ = g ^ (kr & 7);
                uint32_t b0, b1, b2, b3, bb[2];
                ldsm_x4t(b0, b1, b2, b3, kvb + 16384 + kr * 128 + s_ * 16);   // Vhi
                bb[0] = b0; bb[1] = b1; mma16816(o[2 * p], aH, bb);
                bb[0] = b2; bb[1] = b3; mma16816(o[2 * p + 1], aH, bb);
                ldsm_x4t(b0, b1, b2, b3, kvb + 24576 + kr * 128 + s_ * 16);   // Vlo
                bb[0] = b0; bb[1] = b1; mma16816(o[2 * p], aH, bb);
                bb[0] = b2; bb[1] = b3; mma16816(o[2 * p + 1], aH, bb);
            }
        }
    }

    // ---- finalize: denom = exp(-m) + sum(e); write g_a2 [hi|hi]
    ls0 += __shfl_xor_sync(0xffffffffu, ls0, 1);
    ls0 += __shfl_xor_sync(0xffffffffu, ls0, 2);
    ls1 += __shfl_xor_sync(0xffffffffu, ls1, 1);
    ls1 += __shfl_xor_sync(0xffffffffu, ls1, 2);
    float inv0 = 1.0f / (__expf(-mr0) + ls0);
    float inv1 = 1.0f / (__expf(-mr1) + ls1);
    const int row0 = (q0 + w * 16 + rA) * BATCH + bI;
    const int row1 = (q0 + w * 16 + rA + 8) * BATCH + bI;
#pragma unroll
    for (int nf = 0; nf < 8; nf++) {
        int col = h * 64 + nf * 8 + cA;
        unsigned hp;
        hp = pack_h(__float2half(o[nf][0] * inv0), __float2half(o[nf][1] * inv0));
        *(unsigned*)(g_a2 + (size_t)row0 * 2048 + col)        = hp;
        *(unsigned*)(g_a2 + (size_t)row0 * 2048 + 1024 + col) = hp;
        hp = pack_h(__float2half(o[nf][2] * inv1), __float2half(o[nf][3] * inv1));
        *(unsigned*)(g_a2 + (size_t)row1 * 2048 + col)        = hp;
        *(unsigned*)(g_a2 + (size_t)row1 * 2048 + 1024 + col) = hp;
    }
}

// ===========================================================================
extern "C" void kernel_launch(void* const* d_in, const int* in_sizes, int n_in,
                              void* d_out, int out_size)
{
    const float* x     = (const float*)d_in[0];
    const float* ab    = (const float*)d_in[1];
    const float* abm   = (const float*)d_in[2];
    const int*   kpm   = (const int*)d_in[3];
    const float* W_in  = (const float*)d_in[4];
    const float* b_in  = (const float*)d_in[5];
    const float* W_out = (const float*)d_in[6];
    const float* b_out = (const float*)d_in[7];
    float* out = (float*)d_out;

    __half *a2, *w2in, *w2out;
    cudaGetSymbolAddress((void**)&a2,    g_a2);
    cudaGetSymbolAddress((void**)&w2in,  g_w2in);
    cudaGetSymbolAddress((void**)&w2out, g_w2out);

    cudaFuncSetAttribute(attn_mma, cudaFuncAttributeMaxDynamicSharedMemorySize, ATT_SMEM);
    cudaFuncSetAttribute(gemm_ms<0>, cudaFuncAttributeMaxDynamicSharedMemorySize, GEMM_SMEM);
    cudaFuncSetAttribute(gemm_ms<1>, cudaFuncAttributeMaxDynamicSharedMemorySize, GEMM_SMEM);

    // 0) split conversions (weights + x)
    split_kernel<1><<<3072 * 2, 256>>>(W_in,  w2in);
    split_kernel<1><<<1024 * 2, 256>>>(W_out, w2out);
    split_kernel<0><<<4096 * 2, 256>>>(x, a2);
    // 1) QKV projection -> q (hi) / k,v (hi+lo) fp16 planes
    gemm_ms<0><<<dim3(24, 32), 128, GEMM_SMEM>>>(b_in, nullptr);
    // 2) tensor-core fused attention -> g_a2 ([hi|hi] format)
    attn_mma<<<dim3(8, NBH), 256, ATT_SMEM>>>(ab, abm, kpm);
    // 3) output projection
    gemm_ms<1><<<dim3(8, 32), 128, GEMM_SMEM>>>(b_out, out);
}

// round 16
// speedup vs baseline: 1.1132x; 1.1132x over previous
#include <cuda_runtime.h>
#include <cuda_fp16.h>
#include <cstdint>
#include <cstddef>

// Problem constants: S=1024, B=4, E=1024, H=16, D=64
#define S_LEN   1024
#define BATCH   4
#define NHEADS  16
#define DHEAD   64
#define NBH     64          // BATCH*NHEADS
#define NROWS   4096        // S*B
#define EMB     1024

typedef unsigned long long ull;

// ---------------- scratch (device globals; no allocation allowed) ----------
// fp16 2-pass split operands (K_eff = 2048):
//   A2 = [Ahi | Ahi]  (activations: hi duplicated),  W2 = [Whi | Wlo]
//   dot(A2,W2) = Ahi.Whi + Ahi.Wlo   (drops Alo.Whi ~ 2^-12 relative)
__device__ __half g_a2   [(size_t)4096 * 2048];
__device__ __half g_w2in [(size_t)3072 * 2048];
__device__ __half g_w2out[(size_t)1024 * 2048];

// q: fp16 hi-only [bh][s][64]; k/v: fp16 hi+lo planes [bh][plane][s][64]
__device__ __half g_qh[(size_t)NBH * S_LEN * DHEAD];
__device__ __half g_k2[(size_t)NBH * 2 * S_LEN * DHEAD];
__device__ __half g_v2[(size_t)NBH * 2 * S_LEN * DHEAD];

// ---------------- baseline-PTX async-copy / ldmatrix / mma -----------------
__device__ __forceinline__ uint32_t smem_u32(const void* p) {
    uint32_t a;
    asm("{ .reg .u64 t; cvta.to.shared.u64 t, %1; cvt.u32.u64 %0, t; }" : "=r"(a) : "l"(p));
    return a;
}
__device__ __forceinline__ void cp_async16(uint32_t saddr, const void* g) {
    asm volatile("cp.async.cg.shared.global [%0], [%1], 16;" :: "r"(saddr), "l"(g));
}
#define CP_COMMIT() asm volatile("cp.async.commit_group;" ::: "memory")
#define CP_WAIT0()  asm volatile("cp.async.wait_group 0;" ::: "memory")

__device__ __forceinline__ void ldsm_x4(uint32_t& r0, uint32_t& r1, uint32_t& r2, uint32_t& r3,
                                        uint32_t addr) {
    asm volatile("ldmatrix.sync.aligned.m8n8.x4.shared.b16 {%0,%1,%2,%3}, [%4];"
                 : "=r"(r0), "=r"(r1), "=r"(r2), "=r"(r3) : "r"(addr));
}
__device__ __forceinline__ void ldsm_x4t(uint32_t& r0, uint32_t& r1, uint32_t& r2, uint32_t& r3,
                                         uint32_t addr) {
    asm volatile("ldmatrix.sync.aligned.m8n8.x4.trans.shared.b16 {%0,%1,%2,%3}, [%4];"
                 : "=r"(r0), "=r"(r1), "=r"(r2), "=r"(r3) : "r"(addr));
}
__device__ __forceinline__ void mma16816(float* c, const uint32_t* a, const uint32_t* b) {
    asm volatile("mma.sync.aligned.m16n8k16.row.col.f32.f16.f16.f32 "
                 "{%0,%1,%2,%3}, {%4,%5,%6,%7}, {%8,%9}, {%0,%1,%2,%3};"
                 : "+f"(c[0]), "+f"(c[1]), "+f"(c[2]), "+f"(c[3])
                 : "r"(a[0]), "r"(a[1]), "r"(a[2]), "r"(a[3]), "r"(b[0]), "r"(b[1]));
}
__device__ __forceinline__ unsigned pack_h(__half a, __half b) {
    return (unsigned)__half_as_ushort(a) | ((unsigned)__half_as_ushort(b) << 16);
}
__device__ __forceinline__ unsigned pack_hf(float a, float b) {
    return pack_h(__float2half(a), __float2half(b));
}
__device__ __forceinline__ void split2h(float x, float y, unsigned& hi, unsigned& lo) {
    __half hx = __float2half(x), hy = __float2half(y);
    hi = pack_h(hx, hy);
    lo = pack_h(__float2half(x - __half2float(hx)),
                __float2half(y - __half2float(hy)));
}

// ===========================================================================
// Split conversion: src fp32 [rows x 1024] -> dst fp16 [rows x 2048].
// STYLE 0 (activations): [hi | hi].  STYLE 1 (weights): [hi | lo].
// ===========================================================================
template <int STYLE>
__global__ void split_kernel(const float* __restrict__ src, __half* __restrict__ dst)
{
    int idx = blockIdx.x * 256 + threadIdx.x;       // one k-pair
    int r = idx >> 9, kp = idx & 511;
    float2 v = *(const float2*)(src + (size_t)r * 1024 + kp * 2);
    unsigned hp, lp;
    split2h(v.x, v.y, hp, lp);
    size_t base = (size_t)r * 2048 + kp * 2;
    *(unsigned*)(dst + base)        = hp;
    *(unsigned*)(dst + base + 1024) = (STYLE == 0) ? hp : lp;
}

// ===========================================================================
// mma.sync fp16 GEMM over K_eff=2048 (R11/R13-measured: ~140us, tensor 60.7%).
// Block 128x128, 128 threads (4 warps as 2m x 2n), warp tile 64x64.
// BK=64 (128B rows, full swizzle g^(row&7)), 2-stage double buffer in 64KB
// dynamic SMEM -> 32 stages.  UNCHANGED.
// MODE 0: epilogue writes q (fp16 hi), k/v (fp16 hi+lo planes); q scaled 0.125.
// MODE 1: epilogue writes fp32 Cout.
// ===========================================================================
#define GEMM_SMEM 65536     // sA 2x16K at [0,32K), sB 2x16K at [32K,64K)

template <int MODE>
__global__ __launch_bounds__(128, 2)
void gemm_ms(const float* __restrict__ bias, float* __restrict__ Cout)
{
    constexpr int KE = 2048;
    constexpr int NS = KE / 64;     // 32 stages
    extern __shared__ __align__(16) char gsm[];
    const uint32_t sbA = smem_u32(gsm);
    const uint32_t sbB = sbA + 32768;

    const __half* __restrict__ A2 = g_a2;
    const __half* __restrict__ B2 = (MODE == 0) ? g_w2in : g_w2out;

    const int tid = threadIdx.x;
    const int wid = tid >> 5, lane = tid & 31;
    const int wm = wid & 1, wn = wid >> 1;           // 2m x 2n warps
    const int m0 = blockIdx.y * 128, n0 = blockIdx.x * 128;

    float c[4][8][4];
#pragma unroll
    for (int i = 0; i < 4; i++)
#pragma unroll
        for (int j = 0; j < 8; j++)
#pragma unroll
            for (int r = 0; r < 4; r++) c[i][j][r] = 0.f;

    // stage loader: 1024 granules (16B) per matrix; 8 per thread per matrix.
    // swizzle: granule' = granule ^ (row & 7)   (128B rows)
    auto loadStage = [&](int st, int k0) {
        uint32_t baseA = sbA + st * 16384;
        uint32_t baseB = sbB + st * 16384;
#pragma unroll
        for (int h = 0; h < 8; h++) {
            int g = tid + 128 * h;
            int row = g >> 3, gc = g & 7;
            int sw = gc ^ (row & 7);
            cp_async16(baseA + row * 128 + sw * 16, A2 + (size_t)(m0 + row) * KE + k0 + gc * 8);
            cp_async16(baseB + row * 128 + sw * 16, B2 + (size_t)(n0 + row) * KE + k0 + gc * 8);
        }
    };

    loadStage(0, 0);
    CP_COMMIT();

    for (int s = 0; s < NS; s++) {
        CP_WAIT0();
        __syncthreads();
        if (s + 1 < NS) {
            loadStage((s + 1) & 1, (s + 1) * 64);
            CP_COMMIT();
        }
        const int st = s & 1;
        const uint32_t baseA = sbA + st * 16384;
        const uint32_t baseB = sbB + st * 16384;

#pragma unroll
        for (int j = 0; j < 4; j++) {          // four k16 sub-steps
            uint32_t a[4][4];
#pragma unroll
            for (int mf = 0; mf < 4; mf++) {
                int row = wm * 64 + mf * 16 + (lane & 15);
                int g = j * 2 + (lane >> 4);
                int sw = g ^ (row & 7);
                ldsm_x4(a[mf][0], a[mf][1], a[mf][2], a[mf][3], baseA + row * 128 + sw * 16);
            }
            uint32_t b[8][2];
#pragma unroll
            for (int p = 0; p < 4; p++) {      // pair of n8 frags per ldsm.x4
                int row = wn * 64 + p * 16 + (lane & 7) + ((lane >> 4) << 3);
                int g = j * 2 + ((lane >> 3) & 1);
                int sw = g ^ (row & 7);
                uint32_t r0, r1, r2, r3;
                ldsm_x4(r0, r1, r2, r3, baseB + row * 128 + sw * 16);
                b[p * 2][0] = r0; b[p * 2][1] = r1;
                b[p * 2 + 1][0] = r2; b[p * 2 + 1][1] = r3;
            }
#pragma unroll
            for (int mf = 0; mf < 4; mf++)
#pragma unroll
                for (int nf = 0; nf < 8; nf++)
                    mma16816(c[mf][nf], a[mf], b[nf]);
        }
        __syncthreads();
    }

    // ---- epilogue: thread holds rows {t/4, t/4+8}, col pair (t%4)*2
#pragma unroll
    for (int mf = 0; mf < 4; mf++) {
#pragma unroll
        for (int nf = 0; nf < 8; nf++) {
            int n = n0 + wn * 64 + nf * 8 + (lane & 3) * 2;
            float2 bb = *(const float2*)(bias + n);
#pragma unroll
            for (int half = 0; half < 2; half++) {
                int m = m0 + wm * 64 + mf * 16 + (lane >> 2) + half * 8;
                float vx = c[mf][nf][half * 2 + 0] + bb.x;
                float vy = c[mf][nf][half * 2 + 1] + bb.y;
                if (MODE == 0) {
                    int sI = m >> 2, bI = m & 3;
                    int h = n / 192, t = n % 192;
                    int bhI = bI * NHEADS + h;
                    if (t < 64) {
                        vx *= 0.125f; vy *= 0.125f;
                        *(unsigned*)(g_qh + (size_t)bhI * 65536 + (size_t)sI * 64 + t)
                            = pack_hf(vx, vy);
                    } else {
                        __half* dst = (t < 128) ? g_k2 : g_v2;
                        int d = (t < 128) ? (t - 64) : (t - 128);
                        unsigned hi, lo;
                        split2h(vx, vy, hi, lo);
                        size_t base = (size_t)bhI * 131072 + (size_t)sI * 64 + d;
                        *(unsigned*)(dst + base)         = hi;
                        *(unsigned*)(dst + base + 65536) = lo;
                    }
                } else {
                    *(float2*)(Cout + (size_t)m * EMB + n) = make_float2(vx, vy);
                }
            }
        }
    }
}

// ===========================================================================
// Tensor-core fused attention, fp16 2-pass math + double-buffered K/V
// (R13-proven) + P KEPT IN REGISTERS via the C-frag == A-frag layout identity
// (FlashAttention-2 trick): for k16-group j,
//   A = {pack(c[2j][0],c[2j][1]), pack(c[2j][2],c[2j][3]),
//        pack(c[2j+1][0],c[2j+1][1]), pack(c[2j+1][2],c[2j+1][3])}
// Removes per-chunk P SMEM stores + ldsm + __syncwarp.  (R14's L2 prefetch
// regressed and is reverted.)
// Block = 128 q rows x full 1024 keys (16 chunks of 64).
// 8 warps; warp w owns q rows [16w,16w+16) -> softmax stats warp-local.
// fp16: scores = Qhi.(Khi+Klo);  O += Phi.(Vhi+Vlo)
// softmax_1 exact via running-max init 0 (phantom +1 = exp(-m_final)).
// SMEM 80KB: Qh 16K | KV buf0 32K | KV buf1 32K   (2 CTA/SM)
//   KV buf layout: Kh +0, Kl +8K, Vh +16K, Vl +24K
// Output written directly in g_a2 [hi|hi] format for gemm_ms<1>.
// ===========================================================================
#define SM_QH  0
#define SM_KV  16384
#define ATT_SMEM 81920

__global__ __launch_bounds__(256, 2)
void attn_mma(const float* __restrict__ abias, const float* __restrict__ amul,
              const int* __restrict__ kpm)
{
    extern __shared__ __align__(16) char sm[];
    const uint32_t sb = smem_u32(sm);
    const int tid = threadIdx.x;
    const int w = tid >> 5, lane = tid & 31;
    const int bh = blockIdx.y;
    const int q0 = blockIdx.x * 128;
    const int bI = bh >> 4, h = bh & 15;

    const __half* qsrc = g_qh + (size_t)bh * 65536;
    const __half* ksrc = g_k2 + (size_t)bh * 131072;
    const __half* vsrc = g_v2 + (size_t)bh * 131072;

    // K/V chunk loader: 2048 granules (2 planes K + 2 planes V), 8/thread
    auto kvload = [&](int buf, int k0) {
        uint32_t base = sb + SM_KV + buf * 32768;
#pragma unroll
        for (int i = 0; i < 8; i++) {
            int g = tid + 256 * i;
            int plane = g >> 9, r = (g >> 3) & 63, gc = g & 7;
            const __half* src = (plane < 2 ? ksrc : vsrc) + (plane & 1) * 65536
                                + (size_t)(k0 + r) * 64 + gc * 8;
            cp_async16(base + plane * 8192 + r * 128 + ((gc ^ (r & 7)) << 4), src);
        }
    };

    // Q hi plane (persists whole kernel): 1024 x 16B granules, swizzle g^(row&7)
#pragma unroll
    for (int i = 0; i < 4; i++) {
        int g = tid + 256 * i;
        int r = g >> 3, gc = g & 7;
        cp_async16(sb + SM_QH + r * 128 + ((gc ^ (r & 7)) << 4),
                   qsrc + (size_t)(q0 + r) * 64 + gc * 8);
    }
    CP_COMMIT();           // group: Q
    kvload(0, 0);
    CP_COMMIT();           // group: KV0

    float o[8][4];
#pragma unroll
    for (int i = 0; i < 8; i++)
#pragma unroll
        for (int r = 0; r < 4; r++) o[i][r] = 0.f;
    float mr0 = 0.f, mr1 = 0.f, ls0 = 0.f, ls1 = 0.f;   // running max/sum (phantom 0)

    const int rA = lane >> 2;          // 0..7: first fragment row
    const int cA = (lane & 3) * 2;     // col pair base

    for (int chunk = 0; chunk < 16; chunk++) {
        const int k0 = chunk * 64;
        CP_WAIT0();            // KV_c (and Q on chunk 0) landed
        __syncthreads();       // visible to all; buf (c+1)&1 free (read finished in c-1)
        if (chunk + 1 < 16) {
            kvload((chunk + 1) & 1, k0 + 64);
            CP_COMMIT();
        }
        const uint32_t kvb = sb + SM_KV + (chunk & 1) * 32768;

        // ---- scores: c = Qhi.(Khi + Klo)
        float c[8][4];
#pragma unroll
        for (int i = 0; i < 8; i++)
#pragma unroll
            for (int r = 0; r < 4; r++) c[i][r] = 0.f;
#pragma unroll
        for (int j = 0; j < 4; j++) {
            uint32_t qH[4];
            {
                int r = w * 16 + (lane & 15);
                int g = j * 2 + (lane >> 4);
                int s_ = g ^ (r & 7);
                ldsm_x4(qH[0], qH[1], qH[2], qH[3], sb + SM_QH + r * 128 + s_ * 16);
            }
#pragma unroll
            for (int p = 0; p < 4; p++) {
                int r = p * 16 + (lane & 7) + ((lane >> 4) << 3);
                int g = j * 2 + ((lane >> 3) & 1);
                int s_ = g ^ (r & 7);
                uint32_t b0, b1, b2, b3, bb[2];
                ldsm_x4(b0, b1, b2, b3, kvb + r * 128 + s_ * 16);            // Khi
                bb[0] = b0; bb[1] = b1; mma16816(c[2 * p], qH, bb);
                bb[0] = b2; bb[1] = b3; mma16816(c[2 * p + 1], qH, bb);
                ldsm_x4(b0, b1, b2, b3, kvb + 8192 + r * 128 + s_ * 16);     // Klo
                bb[0] = b0; bb[1] = b1; mma16816(c[2 * p], qH, bb);
                bb[0] = b2; bb[1] = b3; mma16816(c[2 * p + 1], qH, bb);
            }
        }

        // ---- softmax pass 1: + bias, mask, chunk row-max
        const int qg0 = q0 + w * 16 + rA;
        const size_t bo0 = ((size_t)bh * S_LEN + qg0) * S_LEN + k0 + cA;
        const size_t bo1 = bo0 + (size_t)8 * S_LEN;
        float cm0 = -1e30f, cm1 = -1e30f;
#pragma unroll
        for (int nf = 0; nf < 8; nf++) {
            int2 mk = __ldg((const int2*)(kpm + bI * S_LEN + k0 + nf * 8 + cA));
            float2 bA = __ldg((const float2*)(abias + bo0 + nf * 8));
            float2 bB = __ldg((const float2*)(abias + bo1 + nf * 8));
            c[nf][0] += bA.x; c[nf][1] += bA.y; c[nf][2] += bB.x; c[nf][3] += bB.y;
            if (mk.x) { c[nf][0] = -1e30f; c[nf][2] = -1e30f; }
            if (mk.y) { c[nf][1] = -1e30f; c[nf][3] = -1e30f; }
            cm0 = fmaxf(cm0, fmaxf(c[nf][0], c[nf][1]));
            cm1 = fmaxf(cm1, fmaxf(c[nf][2], c[nf][3]));
        }
        cm0 = fmaxf(cm0, __shfl_xor_sync(0xffffffffu, cm0, 1));
        cm0 = fmaxf(cm0, __shfl_xor_sync(0xffffffffu, cm0, 2));
        cm1 = fmaxf(cm1, __shfl_xor_sync(0xffffffffu, cm1, 1));
        cm1 = fmaxf(cm1, __shfl_xor_sync(0xffffffffu, cm1, 2));
        float nm0 = fmaxf(mr0, cm0), nm1 = fmaxf(mr1, cm1);
        float al0 = __expf(mr0 - nm0), al1 = __expf(mr1 - nm1);
        mr0 = nm0; mr1 = nm1;

        // ---- pass 2: exp, *mul, pack P into A-fragments (registers)
        float s0 = 0.f, s1 = 0.f;
        unsigned pm[8][2];
#pragma unroll
        for (int nf = 0; nf < 8; nf++) {
            float2 mA = __ldg((const float2*)(amul + bo0 + nf * 8));
            float2 mB = __ldg((const float2*)(amul + bo1 + nf * 8));
            float e0 = __expf(c[nf][0] - nm0), e1 = __expf(c[nf][1] - nm0);
            float e2 = __expf(c[nf][2] - nm1), e3 = __expf(c[nf][3] - nm1);
            s0 += e0 + e1; s1 += e2 + e3;
            pm[nf][0] = pack_hf(e0 * mA.x, e1 * mA.y);   // row g,   keys 2t,2t+1
            pm[nf][1] = pack_hf(e2 * mB.x, e3 * mB.y);   // row g+8, keys 2t,2t+1
        }
        ls0 = ls0 * al0 + s0;
        ls1 = ls1 * al1 + s1;
#pragma unroll
        for (int nf = 0; nf < 8; nf++) {
            o[nf][0] *= al0; o[nf][1] *= al0;
            o[nf][2] *= al1; o[nf][3] *= al1;
        }

        // ---- O += Phi.(Vhi + Vlo)  (P from registers; ldmatrix.trans for V)
#pragma unroll
        for (int j = 0; j < 4; j++) {
            uint32_t aP[4] = { pm[2 * j][0], pm[2 * j][1],
                               pm[2 * j + 1][0], pm[2 * j + 1][1] };
#pragma unroll
            for (int p = 0; p < 4; p++) {
                int kr = j * 16 + ((lane >> 3) & 1) * 8 + (lane & 7);
                int g = p * 2 + ((lane >> 4) & 1);
                int s_ = g ^ (kr & 7);
                uint32_t b0, b1, b2, b3, bb[2];
                ldsm_x4t(b0, b1, b2, b3, kvb + 16384 + kr * 128 + s_ * 16);   // Vhi
                bb[0] = b0; bb[1] = b1; mma16816(o[2 * p], aP, bb);
                bb[0] = b2; bb[1] = b3; mma16816(o[2 * p + 1], aP, bb);
                ldsm_x4t(b0, b1, b2, b3, kvb + 24576 + kr * 128 + s_ * 16);   // Vlo
                bb[0] = b0; bb[1] = b1; mma16816(o[2 * p], aP, bb);
                bb[0] = b2; bb[1] = b3; mma16816(o[2 * p + 1], aP, bb);
            }
        }
    }

    // ---- finalize: denom = exp(-m) + sum(e); write g_a2 [hi|hi]
    ls0 += __shfl_xor_sync(0xffffffffu, ls0, 1);
    ls0 += __shfl_xor_sync(0xffffffffu, ls0, 2);
    ls1 += __shfl_xor_sync(0xffffffffu, ls1, 1);
    ls1 += __shfl_xor_sync(0xffffffffu, ls1, 2);
    float inv0 = 1.0f / (__expf(-mr0) + ls0);
    float inv1 = 1.0f / (__expf(-mr1) + ls1);
    const int row0 = (q0 + w * 16 + rA) * BATCH + bI;
    const int row1 = (q0 + w * 16 + rA + 8) * BATCH + bI;
#pragma unroll
    for (int nf = 0; nf < 8; nf++) {
        int col = h * 64 + nf * 8 + cA;
        unsigned hp;
        hp = pack_hf(o[nf][0] * inv0, o[nf][1] * inv0);
        *(unsigned*)(g_a2 + (size_t)row0 * 2048 + col)        = hp;
        *(unsigned*)(g_a2 + (size_t)row0 * 2048 + 1024 + col) = hp;
        hp = pack_hf(o[nf][2] * inv1, o[nf][3] * inv1);
        *(unsigned*)(g_a2 + (size_t)row1 * 2048 + col)        = hp;
        *(unsigned*)(g_a2 + (size_t)row1 * 2048 + 1024 + col) = hp;
    }
}

// ===========================================================================
extern "C" void kernel_launch(void* const* d_in, const int* in_sizes, int n_in,
                              void* d_out, int out_size)
{
    const float* x     = (const float*)d_in[0];
    const float* ab    = (const float*)d_in[1];
    const float* abm   = (const float*)d_in[2];
    const int*   kpm   = (const int*)d_in[3];
    const float* W_in  = (const float*)d_in[4];
    const float* b_in  = (const float*)d_in[5];
    const float* W_out = (const float*)d_in[6];
    const float* b_out = (const float*)d_in[7];
    float* out = (float*)d_out;

    __half *a2, *w2in, *w2out;
    cudaGetSymbolAddress((void**)&a2,    g_a2);
    cudaGetSymbolAddress((void**)&w2in,  g_w2in);
    cudaGetSymbolAddress((void**)&w2out, g_w2out);

    cudaFuncSetAttribute(attn_mma, cudaFuncAttributeMaxDynamicSharedMemorySize, ATT_SMEM);
    cudaFuncSetAttribute(gemm_ms<0>, cudaFuncAttributeMaxDynamicSharedMemorySize, GEMM_SMEM);
    cudaFuncSetAttribute(gemm_ms<1>, cudaFuncAttributeMaxDynamicSharedMemorySize, GEMM_SMEM);

    // 0) split conversions (weights + x)
    split_kernel<1><<<3072 * 2, 256>>>(W_in,  w2in);
    split_kernel<1><<<1024 * 2, 256>>>(W_out, w2out);
    split_kernel<0><<<4096 * 2, 256>>>(x, a2);
    // 1) QKV projection -> q (hi) / k,v (hi+lo) fp16 planes
    gemm_ms<0><<<dim3(24, 32), 128, GEMM_SMEM>>>(b_in, nullptr);
    // 2) tensor-core fused attention -> g_a2 ([hi|hi] format)
    attn_mma<<<dim3(8, NBH), 256, ATT_SMEM>>>(ab, abm, kpm);
    // 3) output projection
    gemm_ms<1><<<dim3(8, 32), 128, GEMM_SMEM>>>(b_out, out);
}